// round 2
// baseline (speedup 1.0000x reference)
#include <cuda_runtime.h>
#include <math.h>

#define NN   20000
#define EE   160000
#define FEE  500000
#define KHOP 3

// ---------------- scratch (static __device__, no allocations) ----------------
__device__ int   g_degi[NN];
__device__ int   g_cnt[NN];
__device__ float g_deginv[NN];
__device__ int   g_rowptr[NN + 1];
__device__ int   g_esrc[EE];
__device__ float g_Q[NN * 64];
__device__ float g_Kp[2][NN * 64];
__device__ float g_M[2][(size_t)NN * 1024];
__device__ float g_hidden[NN * 64];

// ---------------- CSR build ----------------
__global__ void k_init() {
    int i = blockIdx.x * blockDim.x + threadIdx.x;
    if (i < NN) { g_degi[i] = 0; g_cnt[i] = 0; }
}

__global__ void k_hist(const int* __restrict__ col) {
    int e = blockIdx.x * blockDim.x + threadIdx.x;
    if (e < EE) atomicAdd(&g_degi[col[e]], 1);
}

__global__ void k_scan() {
    __shared__ int s[1024];
    int tid = threadIdx.x;
    const int CH = 20;  // 1024*20 = 20480 >= NN
    int base = tid * CH;
    int sum = 0;
    for (int i = 0; i < CH; i++) {
        int idx = base + i;
        if (idx < NN) sum += g_degi[idx];
    }
    s[tid] = sum;
    __syncthreads();
    for (int d = 1; d < 1024; d <<= 1) {
        int v = (tid >= d) ? s[tid - d] : 0;
        __syncthreads();
        s[tid] += v;
        __syncthreads();
    }
    int run = s[tid] - sum;  // exclusive prefix
    for (int i = 0; i < CH; i++) {
        int idx = base + i;
        if (idx < NN) {
            g_rowptr[idx] = run;
            int dg = g_degi[idx];
            g_deginv[idx] = dg > 0 ? 1.0f / (float)dg : 0.0f;
            run += dg;
        }
    }
    if (tid == 0) g_rowptr[NN] = EE;
}

__global__ void k_fill(const int* __restrict__ row, const int* __restrict__ col) {
    int e = blockIdx.x * blockDim.x + threadIdx.x;
    if (e < EE) {
        int c = col[e];
        int p = atomicAdd(&g_cnt[c], 1);
        g_esrc[g_rowptr[c] + p] = row[e];
    }
}

// ---------------- fused node-feature pipeline ----------------
// block = 256 threads handles 64 nodes. Dynamic smem:
//   sX[64*128] | sE[64*64] | sB[64*256]
__global__ void __launch_bounds__(256)
k_node(const float* __restrict__ x, const int* __restrict__ tsteps,
       const float* __restrict__ Wi, const float* __restrict__ bi,
       const float* __restrict__ Wt1, const float* __restrict__ bt1,
       const float* __restrict__ Wt2, const float* __restrict__ bt2,
       const float* __restrict__ WQ, const float* __restrict__ bQ,
       const float* __restrict__ WK, const float* __restrict__ bK,
       const float* __restrict__ WV, const float* __restrict__ bV,
       const float* __restrict__ hopwise) {
    extern __shared__ float sm[];
    float* sX = sm;               // 8192 floats
    float* sE = sm + 64 * 128;    // 4096 floats
    float* sB = sE + 64 * 64;     // 16384 floats
    const int t = threadIdx.x;
    const int nb = blockIdx.x * 64;
    const int lane = t & 31, wid = t >> 5;

    // ---- load x tile (float4, coalesced) ----
    {
        const float4* xv = (const float4*)x;
        float4* sxv = (float4*)sX;
#pragma unroll
        for (int i = 0; i < 8; i++) {
            int idx = t + 256 * i;      // float4 index in tile (2048 total)
            int n = idx >> 5;           // 32 float4 per row
            int c4 = idx & 31;
            float4 v = make_float4(0.f, 0.f, 0.f, 0.f);
            if (nb + n < NN) v = __ldg(xv + (size_t)(nb + n) * 32 + c4);
            sxv[idx] = v;
        }
    }
    // ---- sinusoidal time embedding -> sE ----
    {
        const float negLn = -logf(10000.0f) / 31.0f;
#pragma unroll
        for (int i = 0; i < 16; i++) {
            int idx = t + 256 * i;   // 4096 total
            int n = idx >> 6, d = idx & 63;
            int ts = (nb + n < NN) ? __ldg(tsteps + nb + n) : 0;
            float tsf = (float)ts * 31.25f;  // 4000/128
            int f = d & 31;
            float freq = expf(negLn * (float)f);
            float arg = tsf * freq;
            sE[idx] = (d < 32) ? sinf(arg) : cosf(arg);
        }
    }
    __syncthreads();

    // ---- stage 2: te1 = silu(sE @ Wt1 + bt1) -> sB [64 x 256] ----
    {
        float acc[8][8];
        {
            float4 b0 = __ldg((const float4*)bt1 + lane * 2);
            float4 b1 = __ldg((const float4*)bt1 + lane * 2 + 1);
#pragma unroll
            for (int i = 0; i < 8; i++) {
                acc[i][0] = b0.x; acc[i][1] = b0.y; acc[i][2] = b0.z; acc[i][3] = b0.w;
                acc[i][4] = b1.x; acc[i][5] = b1.y; acc[i][6] = b1.z; acc[i][7] = b1.w;
            }
        }
        for (int k0 = 0; k0 < 64; k0 += 4) {
            float wv[4][8];
#pragma unroll
            for (int r = 0; r < 4; r++) {
                float4 w0 = __ldg((const float4*)(Wt1 + (k0 + r) * 256) + lane * 2);
                float4 w1 = __ldg((const float4*)(Wt1 + (k0 + r) * 256) + lane * 2 + 1);
                wv[r][0] = w0.x; wv[r][1] = w0.y; wv[r][2] = w0.z; wv[r][3] = w0.w;
                wv[r][4] = w1.x; wv[r][5] = w1.y; wv[r][6] = w1.z; wv[r][7] = w1.w;
            }
#pragma unroll
            for (int i = 0; i < 8; i++) {
                float4 a = *(const float4*)(sE + (wid + 8 * i) * 64 + k0);
#pragma unroll
                for (int c = 0; c < 8; c++) {
                    acc[i][c] = fmaf(a.x, wv[0][c],
                                fmaf(a.y, wv[1][c],
                                fmaf(a.z, wv[2][c],
                                fmaf(a.w, wv[3][c], acc[i][c]))));
                }
            }
        }
#pragma unroll
        for (int i = 0; i < 8; i++) {
#pragma unroll
            for (int c = 0; c < 8; c++) {
                float v = acc[i][c];
                v = v / (1.0f + expf(-v));  // silu
                sB[(wid + 8 * i) * 256 + lane * 8 + c] = v;
            }
        }
    }
    __syncthreads();

    // ---- stage 3: te2 = sB @ Wt2 + bt2 -> sE [64 x 64] ----
    {
        float acc[8][2];
        {
            float2 b = __ldg((const float2*)bt2 + lane);
#pragma unroll
            for (int i = 0; i < 8; i++) { acc[i][0] = b.x; acc[i][1] = b.y; }
        }
        for (int k0 = 0; k0 < 256; k0 += 4) {
            float wv[4][2];
#pragma unroll
            for (int r = 0; r < 4; r++) {
                float2 w = __ldg((const float2*)(Wt2 + (k0 + r) * 64) + lane);
                wv[r][0] = w.x; wv[r][1] = w.y;
            }
#pragma unroll
            for (int i = 0; i < 8; i++) {
                float4 a = *(const float4*)(sB + (wid + 8 * i) * 256 + k0);
#pragma unroll
                for (int c = 0; c < 2; c++) {
                    acc[i][c] = fmaf(a.x, wv[0][c],
                                fmaf(a.y, wv[1][c],
                                fmaf(a.z, wv[2][c],
                                fmaf(a.w, wv[3][c], acc[i][c]))));
                }
            }
        }
        __syncthreads();  // everyone done reading sE(stage2 inputs already) & sB
#pragma unroll
        for (int i = 0; i < 8; i++) {
            sE[(wid + 8 * i) * 64 + lane * 2 + 0] = acc[i][0];
            sE[(wid + 8 * i) * 64 + lane * 2 + 1] = acc[i][1];
        }
    }
    __syncthreads();

    // ---- stage 4: h = relu(sX @ Wi + bi + te2) -> sB[0:4096] ----
    {
        float acc[8][2];
        {
            float2 b = __ldg((const float2*)bi + lane);
#pragma unroll
            for (int i = 0; i < 8; i++) { acc[i][0] = b.x; acc[i][1] = b.y; }
        }
        for (int k0 = 0; k0 < 128; k0 += 4) {
            float wv[4][2];
#pragma unroll
            for (int r = 0; r < 4; r++) {
                float2 w = __ldg((const float2*)(Wi + (k0 + r) * 64) + lane);
                wv[r][0] = w.x; wv[r][1] = w.y;
            }
#pragma unroll
            for (int i = 0; i < 8; i++) {
                float4 a = *(const float4*)(sX + (wid + 8 * i) * 128 + k0);
#pragma unroll
                for (int c = 0; c < 2; c++) {
                    acc[i][c] = fmaf(a.x, wv[0][c],
                                fmaf(a.y, wv[1][c],
                                fmaf(a.z, wv[2][c],
                                fmaf(a.w, wv[3][c], acc[i][c]))));
                }
            }
        }
        __syncthreads();  // done reading sB (te1) everywhere
#pragma unroll
        for (int i = 0; i < 8; i++) {
#pragma unroll
            for (int c = 0; c < 2; c++) {
                float v = acc[i][c] + sE[(wid + 8 * i) * 64 + lane * 2 + c];
                v = fmaxf(v, 0.0f);
                sB[(wid + 8 * i) * 64 + lane * 2 + c] = v;
            }
        }
    }
    __syncthreads();

    // ---- stage 5: Q,K,V from h ----
    {
        float aq[8][2], ak[8][2], av[8][2];
        {
            float2 bq = __ldg((const float2*)bQ + lane);
            float2 bk = __ldg((const float2*)bK + lane);
            float2 bv = __ldg((const float2*)bV + lane);
#pragma unroll
            for (int i = 0; i < 8; i++) {
                aq[i][0] = bq.x; aq[i][1] = bq.y;
                ak[i][0] = bk.x; ak[i][1] = bk.y;
                av[i][0] = bv.x; av[i][1] = bv.y;
            }
        }
        for (int k0 = 0; k0 < 64; k0 += 4) {
            float wq[4][2], wk[4][2], wvv[4][2];
#pragma unroll
            for (int r = 0; r < 4; r++) {
                float2 a1 = __ldg((const float2*)(WQ + (k0 + r) * 64) + lane);
                float2 a2 = __ldg((const float2*)(WK + (k0 + r) * 64) + lane);
                float2 a3 = __ldg((const float2*)(WV + (k0 + r) * 64) + lane);
                wq[r][0] = a1.x; wq[r][1] = a1.y;
                wk[r][0] = a2.x; wk[r][1] = a2.y;
                wvv[r][0] = a3.x; wvv[r][1] = a3.y;
            }
#pragma unroll
            for (int i = 0; i < 8; i++) {
                float4 a = *(const float4*)(sB + (wid + 8 * i) * 64 + k0);
#pragma unroll
                for (int c = 0; c < 2; c++) {
                    aq[i][c] = fmaf(a.x, wq[0][c], fmaf(a.y, wq[1][c], fmaf(a.z, wq[2][c], fmaf(a.w, wq[3][c], aq[i][c]))));
                    ak[i][c] = fmaf(a.x, wk[0][c], fmaf(a.y, wk[1][c], fmaf(a.z, wk[2][c], fmaf(a.w, wk[3][c], ak[i][c]))));
                    av[i][c] = fmaf(a.x, wvv[0][c], fmaf(a.y, wvv[1][c], fmaf(a.z, wvv[2][c], fmaf(a.w, wvv[3][c], av[i][c]))));
                }
            }
        }
        __syncthreads();  // done reading sB (h)
        float hop0 = __ldg(hopwise);
#pragma unroll
        for (int i = 0; i < 8; i++) {
            int nl = wid + 8 * i;
            int g = nb + nl;
#pragma unroll
            for (int c = 0; c < 2; c++) {
                int cc = lane * 2 + c;
                float q = aq[i][c]; q = (q > 0.f) ? q + 1.f : expf(q);
                float kk = ak[i][c]; kk = (kk > 0.f) ? kk + 1.f : expf(kk);
                float vv = av[i][c];
                sB[4096 + nl * 64 + cc] = kk;
                sB[8192 + nl * 64 + cc] = vv;
                if (g < NN) {
                    g_Q[g * 64 + cc] = q;
                    g_Kp[0][g * 64 + cc] = kk;
                    g_hidden[g * 64 + cc] = vv * hop0;
                }
            }
        }
    }
    __syncthreads();

    // ---- stage 6: M0[n,h,i,j] = K[n,h,i] * V[n,h,j] ----
    {
        const float* sK = sB + 4096;
        const float* sV = sB + 8192;
        for (int idx = t; idx < 64 * 1024; idx += 256) {
            int n = idx >> 10;
            int r = idx & 1023;
            int h = r >> 8;
            int ij = r & 255;
            int i = ij >> 4, j = ij & 15;
            int g = nb + n;
            if (g < NN)
                g_M[0][(size_t)g * 1024 + r] = sK[n * 64 + h * 16 + i] * sV[n * 64 + h * 16 + j];
        }
    }
}

// ---------------- propagation: one warp per destination node ----------------
__global__ void k_prop(int cur) {
    int gw = (blockIdx.x * blockDim.x + threadIdx.x) >> 5;
    int lane = threadIdx.x & 31;
    if (gw >= NN) return;
    int s = g_rowptr[gw], e = g_rowptr[gw + 1];
    const float* Mc = g_M[cur];
    float* Mn = g_M[cur ^ 1];
    const float* Kc = g_Kp[cur];
    float* Kn = g_Kp[cur ^ 1];

    float4 acc[8];
#pragma unroll
    for (int u = 0; u < 8; u++) acc[u] = make_float4(0.f, 0.f, 0.f, 0.f);
    float4 ack = make_float4(0.f, 0.f, 0.f, 0.f);

    for (int p = s; p < e; p++) {
        int r = g_esrc[p];
        float w = __ldg(&g_deginv[r]);
        const float4* src = (const float4*)(Mc + (size_t)r * 1024);
#pragma unroll
        for (int u = 0; u < 8; u++) {
            float4 v = __ldg(src + lane + 32 * u);
            acc[u].x = fmaf(v.x, w, acc[u].x);
            acc[u].y = fmaf(v.y, w, acc[u].y);
            acc[u].z = fmaf(v.z, w, acc[u].z);
            acc[u].w = fmaf(v.w, w, acc[u].w);
        }
        if (lane < 16) {
            float4 v = __ldg((const float4*)(Kc + r * 64) + lane);
            ack.x = fmaf(v.x, w, ack.x);
            ack.y = fmaf(v.y, w, ack.y);
            ack.z = fmaf(v.z, w, ack.z);
            ack.w = fmaf(v.w, w, ack.w);
        }
    }
    float4* dst = (float4*)(Mn + (size_t)gw * 1024);
#pragma unroll
    for (int u = 0; u < 8; u++) dst[lane + 32 * u] = acc[u];
    if (lane < 16) ((float4*)(Kn + gw * 64))[lane] = ack;
}

// ---------------- H = Q.M, C = Q.Kf, hidden += gamma*H/C ----------------
__global__ void k_hc(int nxt, int hop,
                     const float* __restrict__ hopwise,
                     const float* __restrict__ headwise) {
    int idx = blockIdx.x * blockDim.x + threadIdx.x;
    if (idx >= NN * 64) return;
    int n = idx >> 6;
    int hj = idx & 63;
    int h = hj >> 4, j = hj & 15;
    const float* M = g_M[nxt] + (size_t)n * 1024 + h * 256 + j;
    const float* Q = g_Q + n * 64 + h * 16;
    const float* Kf = g_Kp[nxt] + n * 64 + h * 16;
    float H = 0.f, C = 1e-5f;
#pragma unroll
    for (int i = 0; i < 16; i++) {
        float q = __ldg(Q + i);
        H = fmaf(q, __ldg(M + i * 16), H);
        C = fmaf(q, __ldg(Kf + i), C);
    }
    // layerwise = softmax over heads of headwise[:, hop]
    float hw[4];
#pragma unroll
    for (int a = 0; a < 4; a++) hw[a] = __ldg(headwise + a * KHOP + hop);
    float m = fmaxf(fmaxf(hw[0], hw[1]), fmaxf(hw[2], hw[3]));
    float e0 = expf(hw[0] - m), e1 = expf(hw[1] - m), e2 = expf(hw[2] - m), e3 = expf(hw[3] - m);
    float ssum = e0 + e1 + e2 + e3;
    float eh = (h == 0) ? e0 : (h == 1) ? e1 : (h == 2) ? e2 : e3;
    float gamma = __ldg(hopwise + hop + 1) * (eh / ssum);
    g_hidden[idx] += gamma * H / C;
}

// ---------------- output projection: hidden[N,64] @ Wo[64,16] + bo ----------------
__global__ void k_proj(const float* __restrict__ Wo, const float* __restrict__ bo,
                       float* __restrict__ outHid) {
    int idx = blockIdx.x * blockDim.x + threadIdx.x;
    if (idx >= NN * 16) return;
    int n = idx >> 4, j = idx & 15;
    float acc = __ldg(bo + j);
    const float* hd = g_hidden + n * 64;
#pragma unroll
    for (int k = 0; k < 64; k++) acc = fmaf(hd[k], __ldg(Wo + k * 16 + j), acc);
    outHid[idx] = acc;
}

// ---------------- edge regression head ----------------
__global__ void k_edge(const int* __restrict__ fsrc, const int* __restrict__ fdst,
                       const float* __restrict__ hid,
                       const float* __restrict__ Wf1, const float* __restrict__ bf1,
                       const float* __restrict__ Wf2, const float* __restrict__ bf2,
                       float* __restrict__ out) {
    __shared__ float sW1[512];
    __shared__ float sb1[16];
    __shared__ float sW2[16];
    __shared__ float sb2;
    int t = threadIdx.x;
    sW1[t] = __ldg(Wf1 + t);
    sW1[t + 256] = __ldg(Wf1 + t + 256);
    if (t < 16) { sb1[t] = __ldg(bf1 + t); sW2[t] = __ldg(Wf2 + t); }
    if (t == 0) sb2 = __ldg(bf2);
    __syncthreads();
    int idx = blockIdx.x * blockDim.x + t;
    if (idx >= FEE) return;
    int s = fsrc[idx], d = fdst[idx];
    float he[32];
    {
        const float4* ps = (const float4*)(hid + s * 16);
        const float4* pd = (const float4*)(hid + d * 16);
#pragma unroll
        for (int u = 0; u < 4; u++) {
            float4 a = __ldg(ps + u);
            he[4 * u + 0] = a.x; he[4 * u + 1] = a.y; he[4 * u + 2] = a.z; he[4 * u + 3] = a.w;
            float4 b = __ldg(pd + u);
            he[16 + 4 * u + 0] = b.x; he[16 + 4 * u + 1] = b.y; he[16 + 4 * u + 2] = b.z; he[16 + 4 * u + 3] = b.w;
        }
    }
    float o = sb2;
#pragma unroll
    for (int j = 0; j < 16; j++) {
        float a = sb1[j];
#pragma unroll
        for (int k = 0; k < 32; k++) a = fmaf(he[k], sW1[k * 16 + j], a);
        a = a / (1.0f + expf(-a));  // silu
        o = fmaf(a, sW2[j], o);
    }
    out[idx] = o;
}

// ---------------- launch ----------------
extern "C" void kernel_launch(void* const* d_in, const int* in_sizes, int n_in,
                              void* d_out, int out_size) {
    (void)in_sizes; (void)n_in; (void)out_size;
    const float* x      = (const float*)d_in[0];
    const int*   ei     = (const int*)d_in[1];
    const int*   fei    = (const int*)d_in[2];
    const int*   tsteps = (const int*)d_in[3];
    const float* Wi  = (const float*)d_in[4];
    const float* bi  = (const float*)d_in[5];
    const float* Wt1 = (const float*)d_in[6];
    const float* bt1 = (const float*)d_in[7];
    const float* Wt2 = (const float*)d_in[8];
    const float* bt2 = (const float*)d_in[9];
    const float* WQ  = (const float*)d_in[10];
    const float* bQ  = (const float*)d_in[11];
    const float* WK  = (const float*)d_in[12];
    const float* bK  = (const float*)d_in[13];
    const float* WV  = (const float*)d_in[14];
    const float* bV  = (const float*)d_in[15];
    const float* Wo  = (const float*)d_in[16];
    const float* bo  = (const float*)d_in[17];
    const float* hopwise  = (const float*)d_in[18];
    const float* headwise = (const float*)d_in[19];
    const float* Wf1 = (const float*)d_in[20];
    const float* bf1 = (const float*)d_in[21];
    const float* Wf2 = (const float*)d_in[22];
    const float* bf2 = (const float*)d_in[23];

    float* out = (float*)d_out;
    float* outHid = out + FEE;

    const int* row = ei;
    const int* col = ei + EE;
    const int* fsrc = fei;
    const int* fdst = fei + FEE;

    k_init<<<(NN + 255) / 256, 256>>>();
    k_hist<<<(EE + 255) / 256, 256>>>(col);
    k_scan<<<1, 1024>>>();
    k_fill<<<(EE + 255) / 256, 256>>>(row, col);

    cudaFuncSetAttribute(k_node, cudaFuncAttributeMaxDynamicSharedMemorySize, 114688);
    k_node<<<(NN + 63) / 64, 256, 114688>>>(x, tsteps, Wi, bi, Wt1, bt1, Wt2, bt2,
                                            WQ, bQ, WK, bK, WV, bV, hopwise);

    int cur = 0;
    for (int hop = 0; hop < KHOP; hop++) {
        k_prop<<<(NN * 32 + 255) / 256, 256>>>(cur);
        k_hc<<<(NN * 64 + 255) / 256, 256>>>(cur ^ 1, hop, hopwise, headwise);
        cur ^= 1;
    }

    k_proj<<<(NN * 16 + 255) / 256, 256>>>(Wo, bo, outHid);
    k_edge<<<(FEE + 255) / 256, 256>>>(fsrc, fdst, outHid, Wf1, bf1, Wf2, bf2, out);
}

// round 3
// speedup vs baseline: 1.3290x; 1.3290x over previous
#include <cuda_runtime.h>
#include <cuda_fp16.h>
#include <math.h>

#define NN   20000
#define EE   160000
#define FEE  500000
#define KHOP 3

// ---------------- scratch (static __device__, no allocations) ----------------
__device__ int     g_degi[NN];
__device__ int     g_cnt[NN];
__device__ float   g_deginv[NN];
__device__ int     g_rowptr[NN + 1];
__device__ int     g_esrc[EE];
__device__ float   g_Q[NN * 64];
__device__ float   g_Kp[2][NN * 64];
__device__ __half2 g_Mh[2][(size_t)NN * 512];   // M in fp16, 512 half2 per node
__device__ float   g_hidden[NN * 64];

// ---------------- CSR build ----------------
__global__ void k_init() {
    int i = blockIdx.x * blockDim.x + threadIdx.x;
    if (i < NN) { g_degi[i] = 0; g_cnt[i] = 0; }
}

__global__ void k_hist(const int* __restrict__ col) {
    int e = blockIdx.x * blockDim.x + threadIdx.x;
    if (e < EE) atomicAdd(&g_degi[col[e]], 1);
}

__global__ void k_scan() {
    __shared__ int s[1024];
    int tid = threadIdx.x;
    const int CH = 20;  // 1024*20 = 20480 >= NN
    int base = tid * CH;
    int sum = 0;
    for (int i = 0; i < CH; i++) {
        int idx = base + i;
        if (idx < NN) sum += g_degi[idx];
    }
    s[tid] = sum;
    __syncthreads();
    for (int d = 1; d < 1024; d <<= 1) {
        int v = (tid >= d) ? s[tid - d] : 0;
        __syncthreads();
        s[tid] += v;
        __syncthreads();
    }
    int run = s[tid] - sum;  // exclusive prefix
    for (int i = 0; i < CH; i++) {
        int idx = base + i;
        if (idx < NN) {
            g_rowptr[idx] = run;
            int dg = g_degi[idx];
            g_deginv[idx] = dg > 0 ? 1.0f / (float)dg : 0.0f;
            run += dg;
        }
    }
    if (tid == 0) g_rowptr[NN] = EE;
}

__global__ void k_fill(const int* __restrict__ row, const int* __restrict__ col) {
    int e = blockIdx.x * blockDim.x + threadIdx.x;
    if (e < EE) {
        int c = col[e];
        int p = atomicAdd(&g_cnt[c], 1);
        g_esrc[g_rowptr[c] + p] = row[e];
    }
}

// ---------------- fused node-feature pipeline ----------------
// block = 256 threads handles 64 nodes. Dynamic smem:
//   sX[64*128] | sE[64*64] | sB[64*256]
__global__ void __launch_bounds__(256)
k_node(const float* __restrict__ x, const int* __restrict__ tsteps,
       const float* __restrict__ Wi, const float* __restrict__ bi,
       const float* __restrict__ Wt1, const float* __restrict__ bt1,
       const float* __restrict__ Wt2, const float* __restrict__ bt2,
       const float* __restrict__ WQ, const float* __restrict__ bQ,
       const float* __restrict__ WK, const float* __restrict__ bK,
       const float* __restrict__ WV, const float* __restrict__ bV,
       const float* __restrict__ hopwise) {
    extern __shared__ float sm[];
    float* sX = sm;               // 8192 floats
    float* sE = sm + 64 * 128;    // 4096 floats
    float* sB = sE + 64 * 64;     // 16384 floats
    const int t = threadIdx.x;
    const int nb = blockIdx.x * 64;
    const int lane = t & 31, wid = t >> 5;

    // ---- load x tile (float4, coalesced) ----
    {
        const float4* xv = (const float4*)x;
        float4* sxv = (float4*)sX;
#pragma unroll
        for (int i = 0; i < 8; i++) {
            int idx = t + 256 * i;      // float4 index in tile (2048 total)
            int n = idx >> 5;           // 32 float4 per row
            int c4 = idx & 31;
            float4 v = make_float4(0.f, 0.f, 0.f, 0.f);
            if (nb + n < NN) v = __ldg(xv + (size_t)(nb + n) * 32 + c4);
            sxv[idx] = v;
        }
    }
    // ---- sinusoidal time embedding -> sE ----
    {
        const float negLn = -logf(10000.0f) / 31.0f;
#pragma unroll
        for (int i = 0; i < 16; i++) {
            int idx = t + 256 * i;   // 4096 total
            int n = idx >> 6, d = idx & 63;
            int ts = (nb + n < NN) ? __ldg(tsteps + nb + n) : 0;
            float tsf = (float)ts * 31.25f;  // 4000/128
            int f = d & 31;
            float freq = expf(negLn * (float)f);
            float arg = tsf * freq;
            sE[idx] = (d < 32) ? sinf(arg) : cosf(arg);
        }
    }
    __syncthreads();

    // ---- stage 2: te1 = silu(sE @ Wt1 + bt1) -> sB [64 x 256] ----
    {
        float acc[8][8];
        {
            float4 b0 = __ldg((const float4*)bt1 + lane * 2);
            float4 b1 = __ldg((const float4*)bt1 + lane * 2 + 1);
#pragma unroll
            for (int i = 0; i < 8; i++) {
                acc[i][0] = b0.x; acc[i][1] = b0.y; acc[i][2] = b0.z; acc[i][3] = b0.w;
                acc[i][4] = b1.x; acc[i][5] = b1.y; acc[i][6] = b1.z; acc[i][7] = b1.w;
            }
        }
        for (int k0 = 0; k0 < 64; k0 += 4) {
            float wv[4][8];
#pragma unroll
            for (int r = 0; r < 4; r++) {
                float4 w0 = __ldg((const float4*)(Wt1 + (k0 + r) * 256) + lane * 2);
                float4 w1 = __ldg((const float4*)(Wt1 + (k0 + r) * 256) + lane * 2 + 1);
                wv[r][0] = w0.x; wv[r][1] = w0.y; wv[r][2] = w0.z; wv[r][3] = w0.w;
                wv[r][4] = w1.x; wv[r][5] = w1.y; wv[r][6] = w1.z; wv[r][7] = w1.w;
            }
#pragma unroll
            for (int i = 0; i < 8; i++) {
                float4 a = *(const float4*)(sE + (wid + 8 * i) * 64 + k0);
#pragma unroll
                for (int c = 0; c < 8; c++) {
                    acc[i][c] = fmaf(a.x, wv[0][c],
                                fmaf(a.y, wv[1][c],
                                fmaf(a.z, wv[2][c],
                                fmaf(a.w, wv[3][c], acc[i][c]))));
                }
            }
        }
#pragma unroll
        for (int i = 0; i < 8; i++) {
#pragma unroll
            for (int c = 0; c < 8; c++) {
                float v = acc[i][c];
                v = v / (1.0f + expf(-v));  // silu
                sB[(wid + 8 * i) * 256 + lane * 8 + c] = v;
            }
        }
    }
    __syncthreads();

    // ---- stage 3: te2 = sB @ Wt2 + bt2 -> sE [64 x 64] ----
    {
        float acc[8][2];
        {
            float2 b = __ldg((const float2*)bt2 + lane);
#pragma unroll
            for (int i = 0; i < 8; i++) { acc[i][0] = b.x; acc[i][1] = b.y; }
        }
        for (int k0 = 0; k0 < 256; k0 += 4) {
            float wv[4][2];
#pragma unroll
            for (int r = 0; r < 4; r++) {
                float2 w = __ldg((const float2*)(Wt2 + (k0 + r) * 64) + lane);
                wv[r][0] = w.x; wv[r][1] = w.y;
            }
#pragma unroll
            for (int i = 0; i < 8; i++) {
                float4 a = *(const float4*)(sB + (wid + 8 * i) * 256 + k0);
#pragma unroll
                for (int c = 0; c < 2; c++) {
                    acc[i][c] = fmaf(a.x, wv[0][c],
                                fmaf(a.y, wv[1][c],
                                fmaf(a.z, wv[2][c],
                                fmaf(a.w, wv[3][c], acc[i][c]))));
                }
            }
        }
        __syncthreads();
#pragma unroll
        for (int i = 0; i < 8; i++) {
            sE[(wid + 8 * i) * 64 + lane * 2 + 0] = acc[i][0];
            sE[(wid + 8 * i) * 64 + lane * 2 + 1] = acc[i][1];
        }
    }
    __syncthreads();

    // ---- stage 4: h = relu(sX @ Wi + bi + te2) -> sB[0:4096] ----
    {
        float acc[8][2];
        {
            float2 b = __ldg((const float2*)bi + lane);
#pragma unroll
            for (int i = 0; i < 8; i++) { acc[i][0] = b.x; acc[i][1] = b.y; }
        }
        for (int k0 = 0; k0 < 128; k0 += 4) {
            float wv[4][2];
#pragma unroll
            for (int r = 0; r < 4; r++) {
                float2 w = __ldg((const float2*)(Wi + (k0 + r) * 64) + lane);
                wv[r][0] = w.x; wv[r][1] = w.y;
            }
#pragma unroll
            for (int i = 0; i < 8; i++) {
                float4 a = *(const float4*)(sX + (wid + 8 * i) * 128 + k0);
#pragma unroll
                for (int c = 0; c < 2; c++) {
                    acc[i][c] = fmaf(a.x, wv[0][c],
                                fmaf(a.y, wv[1][c],
                                fmaf(a.z, wv[2][c],
                                fmaf(a.w, wv[3][c], acc[i][c]))));
                }
            }
        }
        __syncthreads();
#pragma unroll
        for (int i = 0; i < 8; i++) {
#pragma unroll
            for (int c = 0; c < 2; c++) {
                float v = acc[i][c] + sE[(wid + 8 * i) * 64 + lane * 2 + c];
                v = fmaxf(v, 0.0f);
                sB[(wid + 8 * i) * 64 + lane * 2 + c] = v;
            }
        }
    }
    __syncthreads();

    // ---- stage 5: Q,K,V from h ----
    {
        float aq[8][2], ak[8][2], av[8][2];
        {
            float2 bq = __ldg((const float2*)bQ + lane);
            float2 bk = __ldg((const float2*)bK + lane);
            float2 bv = __ldg((const float2*)bV + lane);
#pragma unroll
            for (int i = 0; i < 8; i++) {
                aq[i][0] = bq.x; aq[i][1] = bq.y;
                ak[i][0] = bk.x; ak[i][1] = bk.y;
                av[i][0] = bv.x; av[i][1] = bv.y;
            }
        }
        for (int k0 = 0; k0 < 64; k0 += 4) {
            float wq[4][2], wk[4][2], wvv[4][2];
#pragma unroll
            for (int r = 0; r < 4; r++) {
                float2 a1 = __ldg((const float2*)(WQ + (k0 + r) * 64) + lane);
                float2 a2 = __ldg((const float2*)(WK + (k0 + r) * 64) + lane);
                float2 a3 = __ldg((const float2*)(WV + (k0 + r) * 64) + lane);
                wq[r][0] = a1.x; wq[r][1] = a1.y;
                wk[r][0] = a2.x; wk[r][1] = a2.y;
                wvv[r][0] = a3.x; wvv[r][1] = a3.y;
            }
#pragma unroll
            for (int i = 0; i < 8; i++) {
                float4 a = *(const float4*)(sB + (wid + 8 * i) * 64 + k0);
#pragma unroll
                for (int c = 0; c < 2; c++) {
                    aq[i][c] = fmaf(a.x, wq[0][c], fmaf(a.y, wq[1][c], fmaf(a.z, wq[2][c], fmaf(a.w, wq[3][c], aq[i][c]))));
                    ak[i][c] = fmaf(a.x, wk[0][c], fmaf(a.y, wk[1][c], fmaf(a.z, wk[2][c], fmaf(a.w, wk[3][c], ak[i][c]))));
                    av[i][c] = fmaf(a.x, wvv[0][c], fmaf(a.y, wvv[1][c], fmaf(a.z, wvv[2][c], fmaf(a.w, wvv[3][c], av[i][c]))));
                }
            }
        }
        __syncthreads();
        float hop0 = __ldg(hopwise);
#pragma unroll
        for (int i = 0; i < 8; i++) {
            int nl = wid + 8 * i;
            int g = nb + nl;
#pragma unroll
            for (int c = 0; c < 2; c++) {
                int cc = lane * 2 + c;
                float q = aq[i][c]; q = (q > 0.f) ? q + 1.f : expf(q);
                float kk = ak[i][c]; kk = (kk > 0.f) ? kk + 1.f : expf(kk);
                float vv = av[i][c];
                sB[4096 + nl * 64 + cc] = kk;
                sB[8192 + nl * 64 + cc] = vv;
                if (g < NN) {
                    g_Q[g * 64 + cc] = q;
                    g_Kp[0][g * 64 + cc] = kk;
                    g_hidden[g * 64 + cc] = vv * hop0;
                }
            }
        }
    }
    __syncthreads();

    // ---- stage 6: M0[n,h,i,j] = K[n,h,i] * V[n,h,j], stored as half2 ----
    {
        const float* sK = sB + 4096;
        const float* sV = sB + 8192;
        for (int idx = t; idx < 64 * 512; idx += 256) {
            int n = idx >> 9;
            int r2 = idx & 511;           // half2 index within node
            int h = r2 >> 7;
            int rem = r2 & 127;
            int i = rem >> 3;
            int j2 = (rem & 7) * 2;
            int g = nb + n;
            if (g < NN) {
                float kk = sK[n * 64 + h * 16 + i];
                float v0 = sV[n * 64 + h * 16 + j2];
                float v1 = sV[n * 64 + h * 16 + j2 + 1];
                g_Mh[0][(size_t)g * 512 + r2] = __floats2half2_rn(kk * v0, kk * v1);
            }
        }
    }
}

// ---------------- fused propagation + H/C + hidden update ----------------
// One warp per destination node. fp16 M gather with fp32 accumulation.
// Element layout per node (1024): r = h*256 + i*16 + j.
// Lane loads uint4 (8 halfs) at vec index lane+32u => elems 8*(lane+32u)+c:
//   h = u, i = lane>>1, j = 8*(lane&1)+c.
__global__ void __launch_bounds__(256)
k_prop(int cur, int hop, int last,
       const float* __restrict__ hopwise, const float* __restrict__ headwise) {
    int gw = (blockIdx.x * 256 + threadIdx.x) >> 5;
    int lane = threadIdx.x & 31;
    if (gw >= NN) return;
    int s = g_rowptr[gw], e = g_rowptr[gw + 1];
    const uint4* Mc = (const uint4*)g_Mh[cur];
    const float* Kc = g_Kp[cur];

    float acc[4][8];
#pragma unroll
    for (int u = 0; u < 4; u++)
#pragma unroll
        for (int c = 0; c < 8; c++) acc[u][c] = 0.f;
    float4 ack = make_float4(0.f, 0.f, 0.f, 0.f);

    for (int p = s; p < e; p++) {
        int r = __ldg(g_esrc + p);
        float w = __ldg(g_deginv + r);
        const uint4* src = Mc + (size_t)r * 128 + lane;
#pragma unroll
        for (int u = 0; u < 4; u++) {
            uint4 v = __ldg(src + 32 * u);
            const __half2* hv = (const __half2*)&v;
#pragma unroll
            for (int c2 = 0; c2 < 4; c2++) {
                float2 f = __half22float2(hv[c2]);
                acc[u][2 * c2]     = fmaf(f.x, w, acc[u][2 * c2]);
                acc[u][2 * c2 + 1] = fmaf(f.y, w, acc[u][2 * c2 + 1]);
            }
        }
        if (lane < 16) {
            float4 kv = __ldg((const float4*)(Kc + r * 64) + lane);
            ack.x = fmaf(kv.x, w, ack.x);
            ack.y = fmaf(kv.y, w, ack.y);
            ack.z = fmaf(kv.z, w, ack.z);
            ack.w = fmaf(kv.w, w, ack.w);
        }
    }

    // write propagated M/Kf (skip on last hop — nobody consumes them)
    if (!last) {
        uint4* dst = (uint4*)g_Mh[cur ^ 1] + (size_t)gw * 128 + lane;
#pragma unroll
        for (int u = 0; u < 4; u++) {
            uint4 o;
            __half2* ho = (__half2*)&o;
#pragma unroll
            for (int c2 = 0; c2 < 4; c2++)
                ho[c2] = __floats2half2_rn(acc[u][2 * c2], acc[u][2 * c2 + 1]);
            dst[32 * u] = o;
        }
        if (lane < 16) ((float4*)(g_Kp[cur ^ 1] + gw * 64))[lane] = ack;
    }

    // ---- C[h] = Q[h,:].Kf[h,:] (Kf distributed on lanes 0..15: h=lane>>2, i=4*(lane&3)+c)
    const float* Q = g_Q + gw * 64;
    float cpart = 0.f;
    if (lane < 16) {
        float4 qc = __ldg((const float4*)Q + lane);
        cpart = qc.x * ack.x + qc.y * ack.y + qc.z * ack.z + qc.w * ack.w;
    }
    cpart += __shfl_xor_sync(0xFFFFFFFFu, cpart, 1);
    cpart += __shfl_xor_sync(0xFFFFFFFFu, cpart, 2);
    cpart += __shfl_xor_sync(0xFFFFFFFFu, cpart, 16);
    // now lanes {4h+m, 16+4h+m} hold C[h]

    // ---- H[h][j] = sum_i Q[h,i]*M[h,i,j] ; reduce over i = lane>>1 (xor 2,4,8,16)
    float hp[4][8];
    {
        int i = lane >> 1;
#pragma unroll
        for (int u = 0; u < 4; u++) {
            float qh = __ldg(Q + u * 16 + i);
#pragma unroll
            for (int c = 0; c < 8; c++) hp[u][c] = qh * acc[u][c];
        }
    }
#pragma unroll
    for (int m = 2; m <= 16; m <<= 1) {
#pragma unroll
        for (int u = 0; u < 4; u++)
#pragma unroll
            for (int c = 0; c < 8; c++)
                hp[u][c] += __shfl_xor_sync(0xFFFFFFFFu, hp[u][c], m);
    }

    // Csel for this lane's head h = lane>>1 (only meaningful for lane<8)
    float Csel = __shfl_sync(0xFFFFFFFFu, cpart, ((lane >> 1) & 3) * 4) + 1e-5f;

    // gamma[h] = hopwise[hop+1] * softmax_over_heads(headwise[:,hop])[h]
    float hw0 = __ldg(headwise + 0 * KHOP + hop);
    float hw1 = __ldg(headwise + 1 * KHOP + hop);
    float hw2 = __ldg(headwise + 2 * KHOP + hop);
    float hw3 = __ldg(headwise + 3 * KHOP + hop);
    float mx = fmaxf(fmaxf(hw0, hw1), fmaxf(hw2, hw3));
    float e0 = expf(hw0 - mx), e1 = expf(hw1 - mx), e2 = expf(hw2 - mx), e3 = expf(hw3 - mx);
    float ssum = e0 + e1 + e2 + e3;
    float hopw = __ldg(hopwise + hop + 1);

    if (lane < 8) {
        int h = lane >> 1;
        int jb = (lane & 1) * 8;
        float eh = (h == 0) ? e0 : (h == 1) ? e1 : (h == 2) ? e2 : e3;
        float scale = hopw * (eh / ssum) / Csel;
        float hv[8];
#pragma unroll
        for (int c = 0; c < 8; c++)
            hv[c] = (h == 0) ? hp[0][c] : (h == 1) ? hp[1][c] : (h == 2) ? hp[2][c] : hp[3][c];
        float* hd = g_hidden + gw * 64 + h * 16 + jb;
        float4 a = *(float4*)hd;
        float4 b = *(float4*)(hd + 4);
        a.x += scale * hv[0]; a.y += scale * hv[1]; a.z += scale * hv[2]; a.w += scale * hv[3];
        b.x += scale * hv[4]; b.y += scale * hv[5]; b.z += scale * hv[6]; b.w += scale * hv[7];
        *(float4*)hd = a;
        *(float4*)(hd + 4) = b;
    }
}

// ---------------- output projection: hidden[N,64] @ Wo[64,16] + bo ----------------
__global__ void k_proj(const float* __restrict__ Wo, const float* __restrict__ bo,
                       float* __restrict__ outHid) {
    int idx = blockIdx.x * blockDim.x + threadIdx.x;
    if (idx >= NN * 16) return;
    int n = idx >> 4, j = idx & 15;
    float acc = __ldg(bo + j);
    const float* hd = g_hidden + n * 64;
#pragma unroll
    for (int k = 0; k < 64; k++) acc = fmaf(hd[k], __ldg(Wo + k * 16 + j), acc);
    outHid[idx] = acc;
}

// ---------------- edge regression head ----------------
__global__ void k_edge(const int* __restrict__ fsrc, const int* __restrict__ fdst,
                       const float* __restrict__ hid,
                       const float* __restrict__ Wf1, const float* __restrict__ bf1,
                       const float* __restrict__ Wf2, const float* __restrict__ bf2,
                       float* __restrict__ out) {
    __shared__ float sW1[512];
    __shared__ float sb1[16];
    __shared__ float sW2[16];
    __shared__ float sb2;
    int t = threadIdx.x;
    sW1[t] = __ldg(Wf1 + t);
    sW1[t + 256] = __ldg(Wf1 + t + 256);
    if (t < 16) { sb1[t] = __ldg(bf1 + t); sW2[t] = __ldg(Wf2 + t); }
    if (t == 0) sb2 = __ldg(bf2);
    __syncthreads();
    int idx = blockIdx.x * blockDim.x + t;
    if (idx >= FEE) return;
    int s = fsrc[idx], d = fdst[idx];
    float he[32];
    {
        const float4* ps = (const float4*)(hid + s * 16);
        const float4* pd = (const float4*)(hid + d * 16);
#pragma unroll
        for (int u = 0; u < 4; u++) {
            float4 a = __ldg(ps + u);
            he[4 * u + 0] = a.x; he[4 * u + 1] = a.y; he[4 * u + 2] = a.z; he[4 * u + 3] = a.w;
            float4 b = __ldg(pd + u);
            he[16 + 4 * u + 0] = b.x; he[16 + 4 * u + 1] = b.y; he[16 + 4 * u + 2] = b.z; he[16 + 4 * u + 3] = b.w;
        }
    }
    float o = sb2;
#pragma unroll
    for (int j = 0; j < 16; j++) {
        float a = sb1[j];
#pragma unroll
        for (int k = 0; k < 32; k++) a = fmaf(he[k], sW1[k * 16 + j], a);
        a = a / (1.0f + expf(-a));  // silu
        o = fmaf(a, sW2[j], o);
    }
    out[idx] = o;
}

// ---------------- launch ----------------
extern "C" void kernel_launch(void* const* d_in, const int* in_sizes, int n_in,
                              void* d_out, int out_size) {
    (void)in_sizes; (void)n_in; (void)out_size;
    const float* x      = (const float*)d_in[0];
    const int*   ei     = (const int*)d_in[1];
    const int*   fei    = (const int*)d_in[2];
    const int*   tsteps = (const int*)d_in[3];
    const float* Wi  = (const float*)d_in[4];
    const float* bi  = (const float*)d_in[5];
    const float* Wt1 = (const float*)d_in[6];
    const float* bt1 = (const float*)d_in[7];
    const float* Wt2 = (const float*)d_in[8];
    const float* bt2 = (const float*)d_in[9];
    const float* WQ  = (const float*)d_in[10];
    const float* bQ  = (const float*)d_in[11];
    const float* WK  = (const float*)d_in[12];
    const float* bK  = (const float*)d_in[13];
    const float* WV  = (const float*)d_in[14];
    const float* bV  = (const float*)d_in[15];
    const float* Wo  = (const float*)d_in[16];
    const float* bo  = (const float*)d_in[17];
    const float* hopwise  = (const float*)d_in[18];
    const float* headwise = (const float*)d_in[19];
    const float* Wf1 = (const float*)d_in[20];
    const float* bf1 = (const float*)d_in[21];
    const float* Wf2 = (const float*)d_in[22];
    const float* bf2 = (const float*)d_in[23];

    float* out = (float*)d_out;
    float* outHid = out + FEE;

    const int* row = ei;
    const int* col = ei + EE;
    const int* fsrc = fei;
    const int* fdst = fei + FEE;

    k_init<<<(NN + 255) / 256, 256>>>();
    k_hist<<<(EE + 255) / 256, 256>>>(col);
    k_scan<<<1, 1024>>>();
    k_fill<<<(EE + 255) / 256, 256>>>(row, col);

    cudaFuncSetAttribute(k_node, cudaFuncAttributeMaxDynamicSharedMemorySize, 114688);
    k_node<<<(NN + 63) / 64, 256, 114688>>>(x, tsteps, Wi, bi, Wt1, bt1, Wt2, bt2,
                                            WQ, bQ, WK, bK, WV, bV, hopwise);

    int cur = 0;
    for (int hop = 0; hop < KHOP; hop++) {
        k_prop<<<(NN * 32 + 255) / 256, 256>>>(cur, hop, hop == KHOP - 1, hopwise, headwise);
        cur ^= 1;
    }

    k_proj<<<(NN * 16 + 255) / 256, 256>>>(Wo, bo, outHid);
    k_edge<<<(FEE + 255) / 256, 256>>>(fsrc, fdst, outHid, Wf1, bf1, Wf2, bf2, out);
}

// round 5
// speedup vs baseline: 1.4565x; 1.0960x over previous
#include <cuda_runtime.h>
#include <cuda_fp16.h>
#include <math.h>

#define NN   20000
#define EE   160000
#define FEE  500000
#define KHOP 3

// ---------------- scratch (static __device__, no allocations) ----------------
__device__ int     g_degi[NN];
__device__ int     g_cnt[NN];
__device__ float   g_deginv[NN];
__device__ int     g_rowptr[NN + 1];
__device__ int     g_esrc[EE];
__device__ float   g_ew[EE];
__device__ float   g_temb[128 * 64];
__device__ float   g_Q[NN * 64];
__device__ float   g_Kp[2][NN * 64];
__device__ __half2 g_Mh[2][(size_t)NN * 512];   // M in fp16, 512 half2 per node
__device__ float   g_hidden[NN * 64];

// ---------------- timestep-embedding table (128 distinct timesteps) ----------------
__global__ void __launch_bounds__(64)
k_temb(const float* __restrict__ Wt1, const float* __restrict__ bt1,
       const float* __restrict__ Wt2, const float* __restrict__ bt2) {
    __shared__ float se[64];
    __shared__ float s1[256];
    int ts = blockIdx.x;      // 0..127
    int j = threadIdx.x;      // 0..63
    float tsf = (float)ts * 31.25f;   // 4000/128
    {
        const float negLn = -logf(10000.0f) / 31.0f;
        int f = j & 31;
        float arg = tsf * expf(negLn * (float)f);
        se[j] = (j < 32) ? sinf(arg) : cosf(arg);
    }
    __syncthreads();
    for (int c = j; c < 256; c += 64) {
        float a = __ldg(bt1 + c);
        for (int k = 0; k < 64; k++) a = fmaf(se[k], __ldg(Wt1 + k * 256 + c), a);
        s1[c] = a / (1.0f + expf(-a));   // silu
    }
    __syncthreads();
    {
        float a = __ldg(bt2 + j);
        for (int k = 0; k < 256; k++) a = fmaf(s1[k], __ldg(Wt2 + k * 64 + j), a);
        g_temb[ts * 64 + j] = a;
    }
}

// ---------------- CSR build ----------------
__global__ void k_init() {
    int i = blockIdx.x * blockDim.x + threadIdx.x;
    if (i < NN) { g_degi[i] = 0; g_cnt[i] = 0; }
}

__global__ void k_hist(const int* __restrict__ col) {
    int e = blockIdx.x * blockDim.x + threadIdx.x;
    if (e < EE) atomicAdd(&g_degi[col[e]], 1);
}

__global__ void k_scan() {
    __shared__ int s[1024];
    int tid = threadIdx.x;
    const int CH = 20;  // 1024*20 = 20480 >= NN
    int base = tid * CH;
    int sum = 0;
    for (int i = 0; i < CH; i++) {
        int idx = base + i;
        if (idx < NN) sum += g_degi[idx];
    }
    s[tid] = sum;
    __syncthreads();
    for (int d = 1; d < 1024; d <<= 1) {
        int v = (tid >= d) ? s[tid - d] : 0;
        __syncthreads();
        s[tid] += v;
        __syncthreads();
    }
    int run = s[tid] - sum;  // exclusive prefix
    for (int i = 0; i < CH; i++) {
        int idx = base + i;
        if (idx < NN) {
            g_rowptr[idx] = run;
            int dg = g_degi[idx];
            g_deginv[idx] = dg > 0 ? 1.0f / (float)dg : 0.0f;
            run += dg;
        }
    }
    if (tid == 0) g_rowptr[NN] = EE;
}

__global__ void k_fill(const int* __restrict__ row, const int* __restrict__ col) {
    int e = blockIdx.x * blockDim.x + threadIdx.x;
    if (e < EE) {
        int c = col[e];
        int r = row[e];
        int p = atomicAdd(&g_cnt[c], 1);
        int pos = g_rowptr[c] + p;
        g_esrc[pos] = r;
        g_ew[pos] = g_deginv[r];   // norm = deg_inv[source]; deg over destinations
    }
}

// ---------------- fused node-feature pipeline ----------------
// block = 256 threads handles 64 nodes. Dynamic smem: sX[64*128] | sB[64*192]
__global__ void __launch_bounds__(256)
k_node(const float* __restrict__ x, const int* __restrict__ tsteps,
       const float* __restrict__ Wi, const float* __restrict__ bi,
       const float* __restrict__ WQ, const float* __restrict__ bQ,
       const float* __restrict__ WK, const float* __restrict__ bK,
       const float* __restrict__ WV, const float* __restrict__ bV,
       const float* __restrict__ hopwise) {
    extern __shared__ float sm[];
    float* sX = sm;               // 8192 floats
    float* sB = sm + 64 * 128;    // 12288 floats: h | K | V
    const int t = threadIdx.x;
    const int nb = blockIdx.x * 64;
    const int lane = t & 31, wid = t >> 5;

    // ---- load x tile (float4, coalesced) ----
    {
        const float4* xv = (const float4*)x;
        float4* sxv = (float4*)sX;
#pragma unroll
        for (int i = 0; i < 8; i++) {
            int idx = t + 256 * i;      // float4 index in tile (2048 total)
            int n = idx >> 5;           // 32 float4 per row
            int c4 = idx & 31;
            float4 v = make_float4(0.f, 0.f, 0.f, 0.f);
            if (nb + n < NN) v = __ldg(xv + (size_t)(nb + n) * 32 + c4);
            sxv[idx] = v;
        }
    }
    __syncthreads();

    // ---- stage 4: h = relu(sX @ Wi + bi + temb[ts]) -> sB[0:4096] ----
    {
        float acc[8][2];
        {
            float2 b = __ldg((const float2*)bi + lane);
#pragma unroll
            for (int i = 0; i < 8; i++) { acc[i][0] = b.x; acc[i][1] = b.y; }
        }
        for (int k0 = 0; k0 < 128; k0 += 4) {
            float wv[4][2];
#pragma unroll
            for (int r = 0; r < 4; r++) {
                float2 w = __ldg((const float2*)(Wi + (k0 + r) * 64) + lane);
                wv[r][0] = w.x; wv[r][1] = w.y;
            }
#pragma unroll
            for (int i = 0; i < 8; i++) {
                float4 a = *(const float4*)(sX + (wid + 8 * i) * 128 + k0);
#pragma unroll
                for (int c = 0; c < 2; c++) {
                    acc[i][c] = fmaf(a.x, wv[0][c],
                                fmaf(a.y, wv[1][c],
                                fmaf(a.z, wv[2][c],
                                fmaf(a.w, wv[3][c], acc[i][c]))));
                }
            }
        }
#pragma unroll
        for (int i = 0; i < 8; i++) {
            int rowl = wid + 8 * i;
            int g = nb + rowl;
            int ts = (g < NN) ? __ldg(tsteps + g) : 0;
            const float2* te = (const float2*)(g_temb + ts * 64) + lane;
            float2 tv = *te;
#pragma unroll
            for (int c = 0; c < 2; c++) {
                float v = acc[i][c] + ((c == 0) ? tv.x : tv.y);
                v = fmaxf(v, 0.0f);
                sB[rowl * 64 + lane * 2 + c] = v;
            }
        }
    }
    __syncthreads();

    // ---- stage 5: Q,K,V from h ----
    {
        float aq[8][2], ak[8][2], av[8][2];
        {
            float2 bq = __ldg((const float2*)bQ + lane);
            float2 bk = __ldg((const float2*)bK + lane);
            float2 bv = __ldg((const float2*)bV + lane);
#pragma unroll
            for (int i = 0; i < 8; i++) {
                aq[i][0] = bq.x; aq[i][1] = bq.y;
                ak[i][0] = bk.x; ak[i][1] = bk.y;
                av[i][0] = bv.x; av[i][1] = bv.y;
            }
        }
        for (int k0 = 0; k0 < 64; k0 += 4) {
            float wq[4][2], wk[4][2], wvv[4][2];
#pragma unroll
            for (int r = 0; r < 4; r++) {
                float2 a1 = __ldg((const float2*)(WQ + (k0 + r) * 64) + lane);
                float2 a2 = __ldg((const float2*)(WK + (k0 + r) * 64) + lane);
                float2 a3 = __ldg((const float2*)(WV + (k0 + r) * 64) + lane);
                wq[r][0] = a1.x; wq[r][1] = a1.y;
                wk[r][0] = a2.x; wk[r][1] = a2.y;
                wvv[r][0] = a3.x; wvv[r][1] = a3.y;
            }
#pragma unroll
            for (int i = 0; i < 8; i++) {
                float4 a = *(const float4*)(sB + (wid + 8 * i) * 64 + k0);
#pragma unroll
                for (int c = 0; c < 2; c++) {
                    aq[i][c] = fmaf(a.x, wq[0][c], fmaf(a.y, wq[1][c], fmaf(a.z, wq[2][c], fmaf(a.w, wq[3][c], aq[i][c]))));
                    ak[i][c] = fmaf(a.x, wk[0][c], fmaf(a.y, wk[1][c], fmaf(a.z, wk[2][c], fmaf(a.w, wk[3][c], ak[i][c]))));
                    av[i][c] = fmaf(a.x, wvv[0][c], fmaf(a.y, wvv[1][c], fmaf(a.z, wvv[2][c], fmaf(a.w, wvv[3][c], av[i][c]))));
                }
            }
        }
        __syncthreads();
        float hop0 = __ldg(hopwise);
#pragma unroll
        for (int i = 0; i < 8; i++) {
            int nl = wid + 8 * i;
            int g = nb + nl;
#pragma unroll
            for (int c = 0; c < 2; c++) {
                int cc = lane * 2 + c;
                float q = aq[i][c]; q = (q > 0.f) ? q + 1.f : expf(q);
                float kk = ak[i][c]; kk = (kk > 0.f) ? kk + 1.f : expf(kk);
                float vv = av[i][c];
                sB[4096 + nl * 64 + cc] = kk;
                sB[8192 + nl * 64 + cc] = vv;
                if (g < NN) {
                    g_Q[g * 64 + cc] = q;
                    g_Kp[0][g * 64 + cc] = kk;
                    g_hidden[g * 64 + cc] = vv * hop0;
                }
            }
        }
    }
    __syncthreads();

    // ---- stage 6: M0[n,h,i,j] = K[n,h,i] * V[n,h,j], stored as half2 ----
    {
        const float* sK = sB + 4096;
        const float* sV = sB + 8192;
        for (int idx = t; idx < 64 * 512; idx += 256) {
            int n = idx >> 9;
            int r2 = idx & 511;           // half2 index within node
            int h = r2 >> 7;
            int rem = r2 & 127;
            int i = rem >> 3;
            int j2 = (rem & 7) * 2;
            int g = nb + n;
            if (g < NN) {
                float kk = sK[n * 64 + h * 16 + i];
                float v0 = sV[n * 64 + h * 16 + j2];
                float v1 = sV[n * 64 + h * 16 + j2 + 1];
                g_Mh[0][(size_t)g * 512 + r2] = __floats2half2_rn(kk * v0, kk * v1);
            }
        }
    }
}

// ---------------- fused propagation + H/C + hidden update ----------------
// TWO warps per destination node; warp `half` owns heads {2*half, 2*half+1}
// (M vec indices lane + 32*(2*half+uu), uu in {0,1}).
__global__ void __launch_bounds__(256)
k_prop(int cur, int hop, int last,
       const float* __restrict__ hopwise, const float* __restrict__ headwise) {
    int warp = (blockIdx.x * 256 + threadIdx.x) >> 5;
    int node = warp >> 1;
    int half = warp & 1;
    int lane = threadIdx.x & 31;
    if (node >= NN) return;
    int s = g_rowptr[node], e = g_rowptr[node + 1];
    const uint4* Mc = (const uint4*)g_Mh[cur];
    const float* Kc = g_Kp[cur];

    float acc[2][8];
#pragma unroll
    for (int u = 0; u < 2; u++)
#pragma unroll
        for (int c = 0; c < 8; c++) acc[u][c] = 0.f;
    float4 ack = make_float4(0.f, 0.f, 0.f, 0.f);

    // software-pipelined edge loop: (index, weight) prefetched one edge ahead
    int r_n = 0; float w_n = 0.f;
    if (s < e) { r_n = __ldg(g_esrc + s); w_n = __ldg(g_ew + s); }
    for (int p = s; p < e; p++) {
        int r = r_n; float w = w_n;
        if (p + 1 < e) { r_n = __ldg(g_esrc + p + 1); w_n = __ldg(g_ew + p + 1); }
        const uint4* src = Mc + (size_t)r * 128 + 64 * half + lane;
        uint4 v0 = __ldg(src);
        uint4 v1 = __ldg(src + 32);
        if (lane < 8) {
            float4 kv = __ldg((const float4*)(Kc + r * 64 + half * 32) + lane);
            ack.x = fmaf(kv.x, w, ack.x);
            ack.y = fmaf(kv.y, w, ack.y);
            ack.z = fmaf(kv.z, w, ack.z);
            ack.w = fmaf(kv.w, w, ack.w);
        }
        {
            const __half2* hv = (const __half2*)&v0;
#pragma unroll
            for (int c2 = 0; c2 < 4; c2++) {
                float2 f = __half22float2(hv[c2]);
                acc[0][2 * c2]     = fmaf(f.x, w, acc[0][2 * c2]);
                acc[0][2 * c2 + 1] = fmaf(f.y, w, acc[0][2 * c2 + 1]);
            }
        }
        {
            const __half2* hv = (const __half2*)&v1;
#pragma unroll
            for (int c2 = 0; c2 < 4; c2++) {
                float2 f = __half22float2(hv[c2]);
                acc[1][2 * c2]     = fmaf(f.x, w, acc[1][2 * c2]);
                acc[1][2 * c2 + 1] = fmaf(f.y, w, acc[1][2 * c2 + 1]);
            }
        }
    }

    // write propagated M/Kf (skip on last hop — nobody consumes them)
    if (!last) {
        uint4* dst = (uint4*)g_Mh[cur ^ 1] + (size_t)node * 128 + 64 * half + lane;
#pragma unroll
        for (int u = 0; u < 2; u++) {
            uint4 o;
            __half2* ho = (__half2*)&o;
#pragma unroll
            for (int c2 = 0; c2 < 4; c2++)
                ho[c2] = __floats2half2_rn(acc[u][2 * c2], acc[u][2 * c2 + 1]);
            dst[32 * u] = o;
        }
        if (lane < 8) ((float4*)(g_Kp[cur ^ 1] + node * 64 + half * 32))[lane] = ack;
    }

    // ---- C[h] = Q[h,:].Kf[h,:] on lanes 0..7 (local head = lane>>2) ----
    const float* Q = g_Q + node * 64;
    float cpart = 0.f;
    if (lane < 8) {
        float4 qc = __ldg((const float4*)(Q + half * 32) + lane);
        cpart = qc.x * ack.x + qc.y * ack.y + qc.z * ack.z + qc.w * ack.w;
    }
    cpart += __shfl_xor_sync(0xFFFFFFFFu, cpart, 1);
    cpart += __shfl_xor_sync(0xFFFFFFFFu, cpart, 2);
    // lanes 0-3 hold C[local 0], lanes 4-7 hold C[local 1]

    // ---- H[u][j] = sum_i Q[gh,i]*M[gh,i,j]; i = lane>>1, j = 8*(lane&1)+c ----
    float hp[2][8];
    {
        int i = lane >> 1;
#pragma unroll
        for (int u = 0; u < 2; u++) {
            float qh = __ldg(Q + (2 * half + u) * 16 + i);
#pragma unroll
            for (int c = 0; c < 8; c++) hp[u][c] = qh * acc[u][c];
        }
    }
#pragma unroll
    for (int m = 2; m <= 16; m <<= 1) {
#pragma unroll
        for (int u = 0; u < 2; u++)
#pragma unroll
            for (int c = 0; c < 8; c++)
                hp[u][c] += __shfl_xor_sync(0xFFFFFFFFu, hp[u][c], m);
    }

    // gamma[h] = hopwise[hop+1] * softmax_over_heads(headwise[:,hop])[h]
    float hw0 = __ldg(headwise + 0 * KHOP + hop);
    float hw1 = __ldg(headwise + 1 * KHOP + hop);
    float hw2 = __ldg(headwise + 2 * KHOP + hop);
    float hw3 = __ldg(headwise + 3 * KHOP + hop);
    float mx = fmaxf(fmaxf(hw0, hw1), fmaxf(hw2, hw3));
    float e0 = expf(hw0 - mx), e1 = expf(hw1 - mx), e2 = expf(hw2 - mx), e3 = expf(hw3 - mx);
    float ssum = e0 + e1 + e2 + e3;
    float hopw = __ldg(hopwise + hop + 1);

    float Csel = __shfl_sync(0xFFFFFFFFu, cpart, ((lane >> 1) & 1) * 4) + 1e-5f;

    if (lane < 4) {
        int lh = lane >> 1;            // local head
        int gh = 2 * half + lh;        // global head
        int jb = (lane & 1) * 8;
        float eh = (gh == 0) ? e0 : (gh == 1) ? e1 : (gh == 2) ? e2 : e3;
        float scale = hopw * (eh / ssum) / Csel;
        float hv[8];
#pragma unroll
        for (int c = 0; c < 8; c++) hv[c] = (lh == 0) ? hp[0][c] : hp[1][c];
        float* hd = g_hidden + node * 64 + gh * 16 + jb;
        float4 a = *(float4*)hd;
        float4 b = *(float4*)(hd + 4);
        a.x += scale * hv[0]; a.y += scale * hv[1]; a.z += scale * hv[2]; a.w += scale * hv[3];
        b.x += scale * hv[4]; b.y += scale * hv[5]; b.z += scale * hv[6]; b.w += scale * hv[7];
        *(float4*)hd = a;
        *(float4*)(hd + 4) = b;
    }
}

// ---------------- output projection: hidden[N,64] @ Wo[64,16] + bo ----------------
__global__ void k_proj(const float* __restrict__ Wo, const float* __restrict__ bo,
                       float* __restrict__ outHid) {
    int idx = blockIdx.x * blockDim.x + threadIdx.x;
    if (idx >= NN * 16) return;
    int n = idx >> 4, j = idx & 15;
    float acc = __ldg(bo + j);
    const float* hd = g_hidden + n * 64;
#pragma unroll
    for (int k = 0; k < 64; k++) acc = fmaf(hd[k], __ldg(Wo + k * 16 + j), acc);
    outHid[idx] = acc;
}

// ---------------- edge regression head ----------------
__global__ void k_edge(const int* __restrict__ fsrc, const int* __restrict__ fdst,
                       const float* __restrict__ hid,
                       const float* __restrict__ Wf1, const float* __restrict__ bf1,
                       const float* __restrict__ Wf2, const float* __restrict__ bf2,
                       float* __restrict__ out) {
    __shared__ float sW1[512];
    __shared__ float sb1[16];
    __shared__ float sW2[16];
    __shared__ float sb2;
    int t = threadIdx.x;
    sW1[t] = __ldg(Wf1 + t);
    sW1[t + 256] = __ldg(Wf1 + t + 256);
    if (t < 16) { sb1[t] = __ldg(bf1 + t); sW2[t] = __ldg(Wf2 + t); }
    if (t == 0) sb2 = __ldg(bf2);
    __syncthreads();
    int idx = blockIdx.x * blockDim.x + t;
    if (idx >= FEE) return;
    int s = fsrc[idx], d = fdst[idx];
    float he[32];
    {
        const float4* ps = (const float4*)(hid + s * 16);
        const float4* pd = (const float4*)(hid + d * 16);
#pragma unroll
        for (int u = 0; u < 4; u++) {
            float4 a = __ldg(ps + u);
            he[4 * u + 0] = a.x; he[4 * u + 1] = a.y; he[4 * u + 2] = a.z; he[4 * u + 3] = a.w;
            float4 b = __ldg(pd + u);
            he[16 + 4 * u + 0] = b.x; he[16 + 4 * u + 1] = b.y; he[16 + 4 * u + 2] = b.z; he[16 + 4 * u + 3] = b.w;
        }
    }
    float o = sb2;
#pragma unroll
    for (int j = 0; j < 16; j++) {
        float a = sb1[j];
#pragma unroll
        for (int k = 0; k < 32; k++) a = fmaf(he[k], sW1[k * 16 + j], a);
        a = a / (1.0f + expf(-a));  // silu
        o = fmaf(a, sW2[j], o);
    }
    out[idx] = o;
}

// ---------------- launch ----------------
extern "C" void kernel_launch(void* const* d_in, const int* in_sizes, int n_in,
                              void* d_out, int out_size) {
    (void)in_sizes; (void)n_in; (void)out_size;
    const float* x      = (const float*)d_in[0];
    const int*   ei     = (const int*)d_in[1];
    const int*   fei    = (const int*)d_in[2];
    const int*   tsteps = (const int*)d_in[3];
    const float* Wi  = (const float*)d_in[4];
    const float* bi  = (const float*)d_in[5];
    const float* Wt1 = (const float*)d_in[6];
    const float* bt1 = (const float*)d_in[7];
    const float* Wt2 = (const float*)d_in[8];
    const float* bt2 = (const float*)d_in[9];
    const float* WQ  = (const float*)d_in[10];
    const float* bQ  = (const float*)d_in[11];
    const float* WK  = (const float*)d_in[12];
    const float* bK  = (const float*)d_in[13];
    const float* WV  = (const float*)d_in[14];
    const float* bV  = (const float*)d_in[15];
    const float* Wo  = (const float*)d_in[16];
    const float* bo  = (const float*)d_in[17];
    const float* hopwise  = (const float*)d_in[18];
    const float* headwise = (const float*)d_in[19];
    const float* Wf1 = (const float*)d_in[20];
    const float* bf1 = (const float*)d_in[21];
    const float* Wf2 = (const float*)d_in[22];
    const float* bf2 = (const float*)d_in[23];

    float* out = (float*)d_out;
    float* outHid = out + FEE;

    const int* row = ei;
    const int* col = ei + EE;
    const int* fsrc = fei;
    const int* fdst = fei + FEE;

    k_temb<<<128, 64>>>(Wt1, bt1, Wt2, bt2);
    k_init<<<(NN + 255) / 256, 256>>>();
    k_hist<<<(EE + 255) / 256, 256>>>(col);
    k_scan<<<1, 1024>>>();
    k_fill<<<(EE + 255) / 256, 256>>>(row, col);

    cudaFuncSetAttribute(k_node, cudaFuncAttributeMaxDynamicSharedMemorySize, 81920);
    k_node<<<(NN + 63) / 64, 256, 81920>>>(x, tsteps, Wi, bi,
                                           WQ, bQ, WK, bK, WV, bV, hopwise);

    int cur = 0;
    for (int hop = 0; hop < KHOP; hop++) {
        k_prop<<<(NN * 64 + 255) / 256, 256>>>(cur, hop, hop == KHOP - 1, hopwise, headwise);
        cur ^= 1;
    }

    k_proj<<<(NN * 16 + 255) / 256, 256>>>(Wo, bo, outHid);
    k_edge<<<(FEE + 255) / 256, 256>>>(fsrc, fdst, outHid, Wf1, bf1, Wf2, bf2, out);
}